// round 1
// baseline (speedup 1.0000x reference)
#include <cuda_runtime.h>
#include <math.h>
#include <float.h>
#include <stdint.h>

// Problem constants (GAT_38585986187787)
#define MAX_NODES 100000
#define MAX_EDGES 1600000
#define D_IN 64
#define HEADS 4
#define HC 256   // HEADS * C_OUT

// ---------------------------------------------------------------------------
// Device scratch (no allocations allowed in kernel_launch)
// ---------------------------------------------------------------------------
__device__ float g_xl[(size_t)MAX_NODES * HC];      // 102.4 MB   x @ W
__device__ float g_asrc[MAX_NODES * HEADS];         // 1.6 MB
__device__ float g_adst[MAX_NODES * HEADS];         // 1.6 MB
__device__ float g_max[MAX_NODES * HEADS];          // 1.6 MB  segment max
__device__ float g_den[MAX_NODES * HEADS];          // 1.6 MB  segment sum of exp
__device__ float g_logit[(size_t)MAX_EDGES * HEADS];// 25.6 MB per-edge leaky logits
__device__ int   g_is64;                            // edge_index dtype flag

// ---------------------------------------------------------------------------
// Helpers
// ---------------------------------------------------------------------------
__device__ __forceinline__ void atomicMaxF(float* addr, float v) {
    if (v >= 0.0f) atomicMax((int*)addr, __float_as_int(v));
    else           atomicMin((unsigned int*)addr, __float_as_uint(v));
}

__device__ __forceinline__ void red_add_v4(float* addr, float4 v) {
    asm volatile("red.global.add.v4.f32 [%0], {%1, %2, %3, %4};"
                 :: "l"(addr), "f"(v.x), "f"(v.y), "f"(v.z), "f"(v.w)
                 : "memory");
}

__device__ __forceinline__ long long load_edge(const void* ei, int is64, size_t idx) {
    if (is64) return ((const long long*)ei)[idx];
    return (long long)(((const int*)ei)[idx]);
}

// ---------------------------------------------------------------------------
// 0. Detect edge_index dtype (int64 vs silently-downcast int32)
// ---------------------------------------------------------------------------
__global__ void detect_kernel(const void* ei) {
    const unsigned long long* p = (const unsigned long long*)ei;
    bool ok = true;
#pragma unroll
    for (int i = 0; i < 16; i++) ok = ok && (p[i] < (unsigned long long)MAX_NODES);
    g_is64 = ok ? 1 : 0;
}

// ---------------------------------------------------------------------------
// 1. Init: out = bias broadcast, seg_max = -FLT_MAX, denom = 0
//    idx is a float4 index over out (N*64 float4s).
// ---------------------------------------------------------------------------
__global__ void init_kernel(const float* __restrict__ bias, float* __restrict__ out, int n) {
    int idx = blockIdx.x * blockDim.x + threadIdx.x;
    int total = n * 64;
    if (idx < total) {
        const float4* b4 = (const float4*)bias;
        ((float4*)out)[idx] = b4[idx & 63];
    }
    if (idx < n) {
        ((float4*)g_max)[idx] = make_float4(-FLT_MAX, -FLT_MAX, -FLT_MAX, -FLT_MAX);
        ((float4*)g_den)[idx] = make_float4(0.f, 0.f, 0.f, 0.f);
    }
}

// ---------------------------------------------------------------------------
// 2. GEMM: xl[n, 256] = x[n, 64] @ W[64, 256]
//    Block: 256 threads, 64 rows. W (64KB) + padded x tile (16.6KB) in smem.
//    Thread (tr = t/16, tc = t%16) computes 4 rows x 16 cols (4 quads of 4).
// ---------------------------------------------------------------------------
__global__ void gemm_kernel(const float* __restrict__ x, const float* __restrict__ W, int n) {
    extern __shared__ float sm[];
    float* sW = sm;              // 64*256 floats
    float* sX = sm + 64 * 256;   // 64 rows * 65 (padded)

    int t = threadIdx.x;
    int row0 = blockIdx.x * 64;

    // Load W (coalesced float4)
    const float4* W4 = (const float4*)W;
    float4* sW4 = (float4*)sW;
#pragma unroll
    for (int i = 0; i < 16; i++) sW4[t + i * 256] = W4[t + i * 256];

    // Load x tile with row padding (stride 65) to avoid LDS bank conflicts
#pragma unroll
    for (int i = 0; i < 16; i++) {
        int idx = t + i * 256;
        int r = idx >> 6, c = idx & 63;
        float v = (row0 + r < n) ? x[(size_t)(row0 + r) * D_IN + c] : 0.f;
        sX[r * 65 + c] = v;
    }
    __syncthreads();

    int tr = t >> 4;   // 0..15 -> rows tr*4 .. tr*4+3
    int tc = t & 15;   // 0..15 -> cols q*64 + tc*4 .. +3, q=0..3

    float acc[4][16];
#pragma unroll
    for (int j = 0; j < 4; j++)
#pragma unroll
        for (int i = 0; i < 16; i++) acc[j][i] = 0.f;

#pragma unroll 4
    for (int k = 0; k < 64; k++) {
        float xv[4];
#pragma unroll
        for (int j = 0; j < 4; j++) xv[j] = sX[(tr * 4 + j) * 65 + k];
#pragma unroll
        for (int q = 0; q < 4; q++) {
            float4 w = *(const float4*)(sW + k * 256 + q * 64 + tc * 4);
#pragma unroll
            for (int j = 0; j < 4; j++) {
                acc[j][q * 4 + 0] += xv[j] * w.x;
                acc[j][q * 4 + 1] += xv[j] * w.y;
                acc[j][q * 4 + 2] += xv[j] * w.z;
                acc[j][q * 4 + 3] += xv[j] * w.w;
            }
        }
    }

#pragma unroll
    for (int j = 0; j < 4; j++) {
        int r = row0 + tr * 4 + j;
        if (r < n) {
#pragma unroll
            for (int q = 0; q < 4; q++) {
                float4 v = make_float4(acc[j][q * 4 + 0], acc[j][q * 4 + 1],
                                       acc[j][q * 4 + 2], acc[j][q * 4 + 3]);
                *(float4*)(g_xl + (size_t)r * HC + q * 64 + tc * 4) = v;
            }
        }
    }
}

// ---------------------------------------------------------------------------
// 3. Attention scores: a_src[n,h] = <xl[n,h,:], att_src[h,:]>, same for dst.
//    One warp per node; lane covers 8 channels; 8-lane tree reduction per head.
// ---------------------------------------------------------------------------
__global__ void att_kernel(const float* __restrict__ att_src,
                           const float* __restrict__ att_dst, int n) {
    int w = (blockIdx.x * blockDim.x + threadIdx.x) >> 5;
    int lane = threadIdx.x & 31;
    if (w >= n) return;
    int h = lane >> 3;
    int c = lane * 8;  // global channel offset (h*64 + within-head offset)

    const float* xr = g_xl + (size_t)w * HC + c;
    float4 v0 = *(const float4*)xr;
    float4 v1 = *(const float4*)(xr + 4);
    const float* as = att_src + c;
    const float* ad = att_dst + c;
    float4 s0 = *(const float4*)as, s1 = *(const float4*)(as + 4);
    float4 d0 = *(const float4*)ad, d1 = *(const float4*)(ad + 4);

    float ps = v0.x * s0.x + v0.y * s0.y + v0.z * s0.z + v0.w * s0.w
             + v1.x * s1.x + v1.y * s1.y + v1.z * s1.z + v1.w * s1.w;
    float pd = v0.x * d0.x + v0.y * d0.y + v0.z * d0.z + v0.w * d0.w
             + v1.x * d1.x + v1.y * d1.y + v1.z * d1.z + v1.w * d1.w;

#pragma unroll
    for (int off = 4; off > 0; off >>= 1) {
        ps += __shfl_down_sync(0xffffffff, ps, off);
        pd += __shfl_down_sync(0xffffffff, pd, off);
    }
    if ((lane & 7) == 0) {
        g_asrc[w * HEADS + h] = ps;
        g_adst[w * HEADS + h] = pd;
    }
}

// ---------------------------------------------------------------------------
// 4. Per-edge logits (leaky relu) + segment max (atomic)
// ---------------------------------------------------------------------------
__global__ void logits_kernel(const void* __restrict__ ei, int E) {
    int e = blockIdx.x * blockDim.x + threadIdx.x;
    if (e >= E) return;
    int is64 = g_is64;
    long long s = load_edge(ei, is64, e);
    long long d = load_edge(ei, is64, (size_t)E + e);

    float4 as = *(const float4*)(g_asrc + s * HEADS);
    float4 ad = *(const float4*)(g_adst + d * HEADS);
    float4 l;
    l.x = as.x + ad.x; l.x = (l.x >= 0.f) ? l.x : 0.2f * l.x;
    l.y = as.y + ad.y; l.y = (l.y >= 0.f) ? l.y : 0.2f * l.y;
    l.z = as.z + ad.z; l.z = (l.z >= 0.f) ? l.z : 0.2f * l.z;
    l.w = as.w + ad.w; l.w = (l.w >= 0.f) ? l.w : 0.2f * l.w;
    *(float4*)(g_logit + (size_t)e * HEADS) = l;

    float* m = g_max + d * HEADS;
    atomicMaxF(m + 0, l.x);
    atomicMaxF(m + 1, l.y);
    atomicMaxF(m + 2, l.z);
    atomicMaxF(m + 3, l.w);
}

// ---------------------------------------------------------------------------
// 5. Segment denominator: denom[dst,h] += exp(logit - max)
// ---------------------------------------------------------------------------
__global__ void denom_kernel(const void* __restrict__ ei, int E) {
    int e = blockIdx.x * blockDim.x + threadIdx.x;
    if (e >= E) return;
    int is64 = g_is64;
    long long d = load_edge(ei, is64, (size_t)E + e);

    float4 l = *(const float4*)(g_logit + (size_t)e * HEADS);
    float4 m = *(const float4*)(g_max + d * HEADS);
    float4 ex;
    ex.x = __expf(l.x - m.x);
    ex.y = __expf(l.y - m.y);
    ex.z = __expf(l.z - m.z);
    ex.w = __expf(l.w - m.w);
    red_add_v4(g_den + d * HEADS, ex);
}

// ---------------------------------------------------------------------------
// 6. Aggregate: out[dst] += alpha * xl[src].  One warp per edge.
//    lane covers channels lane*8 .. lane*8+7 (head h = lane>>3).
// ---------------------------------------------------------------------------
__global__ void agg_kernel(const void* __restrict__ ei, int E, float* __restrict__ out) {
    int gw = (blockIdx.x * blockDim.x + threadIdx.x) >> 5;
    int lane = threadIdx.x & 31;
    if (gw >= E) return;
    int is64 = g_is64;
    long long s = load_edge(ei, is64, gw);
    long long d = load_edge(ei, is64, (size_t)E + gw);

    int h = lane >> 3;
    float l = g_logit[(size_t)gw * HEADS + h];
    float m = g_max[d * HEADS + h];
    float den = g_den[d * HEADS + h];
    float alpha = __expf(l - m) / (den + 1e-16f);

    const float4* xs = (const float4*)(g_xl + (size_t)s * HC + lane * 8);
    float4 v0 = xs[0], v1 = xs[1];
    v0.x *= alpha; v0.y *= alpha; v0.z *= alpha; v0.w *= alpha;
    v1.x *= alpha; v1.y *= alpha; v1.z *= alpha; v1.w *= alpha;

    float* po = out + (size_t)d * HC + lane * 8;
    red_add_v4(po, v0);
    red_add_v4(po + 4, v1);
}

// ---------------------------------------------------------------------------
// Launch
// ---------------------------------------------------------------------------
extern "C" void kernel_launch(void* const* d_in, const int* in_sizes, int n_in,
                              void* d_out, int out_size) {
    const float* x        = (const float*)d_in[0];
    const void*  ei       = (const void*)d_in[1];
    const float* W        = (const float*)d_in[2];
    const float* att_src  = (const float*)d_in[3];
    const float* att_dst  = (const float*)d_in[4];
    const float* bias     = (const float*)d_in[5];
    float* out = (float*)d_out;

    int N = in_sizes[0] / D_IN;
    int E = in_sizes[1] / 2;

    detect_kernel<<<1, 1>>>(ei);

    int init_threads = N * 64;  // float4 units over out
    init_kernel<<<(init_threads + 255) / 256, 256>>>(bias, out, N);

    size_t smem = (size_t)64 * 256 * 4 + (size_t)64 * 65 * 4;  // 82176 B
    cudaFuncSetAttribute(gemm_kernel, cudaFuncAttributeMaxDynamicSharedMemorySize, (int)smem);
    gemm_kernel<<<(N + 63) / 64, 256, smem>>>(x, W, N);

    att_kernel<<<(N * 32 + 255) / 256, 256>>>(att_src, att_dst, N);

    logits_kernel<<<(E + 255) / 256, 256>>>(ei, E);
    denom_kernel<<<(E + 255) / 256, 256>>>(ei, E);

    long long agg_threads = (long long)E * 32;
    agg_kernel<<<(int)((agg_threads + 255) / 256), 256>>>(ei, E, out);
}

// round 2
// speedup vs baseline: 1.6649x; 1.6649x over previous
#include <cuda_runtime.h>
#include <math.h>
#include <float.h>
#include <stdint.h>

// Problem constants (GAT_38585986187787)
#define MAX_NODES 100000
#define MAX_EDGES 1600000
#define D_IN 64
#define HEADS 4
#define HC 256   // HEADS * C_OUT

// ---------------------------------------------------------------------------
// Device scratch
// ---------------------------------------------------------------------------
__device__ float g_xl[(size_t)MAX_NODES * HC];      // 102.4 MB   x @ W
__device__ float g_asrc[MAX_NODES * HEADS];         // 1.6 MB
__device__ float g_adst[MAX_NODES * HEADS];         // 1.6 MB
__device__ int   g_cnt[MAX_NODES];                  // in-degree counts
__device__ int   g_off[MAX_NODES + 1];              // CSR offsets (by dst)
__device__ int   g_cur[MAX_NODES];                  // scatter cursors
__device__ int   g_srclist[MAX_EDGES];              // src id per CSR slot
__device__ int   g_is64;                            // edge_index dtype flag

__device__ __forceinline__ long long load_edge(const void* ei, int is64, size_t idx) {
    if (is64) return ((const long long*)ei)[idx];
    return (long long)(((const int*)ei)[idx]);
}

// ---------------------------------------------------------------------------
// 0. Detect edge_index dtype (int64 vs silently-downcast int32)
// ---------------------------------------------------------------------------
__global__ void detect_kernel(const void* ei) {
    const unsigned long long* p = (const unsigned long long*)ei;
    bool ok = true;
#pragma unroll
    for (int i = 0; i < 16; i++) ok = ok && (p[i] < (unsigned long long)MAX_NODES);
    g_is64 = ok ? 1 : 0;
}

// ---------------------------------------------------------------------------
// 1. Init: out = bias broadcast (covers deg-0 nodes), zero degree counters
// ---------------------------------------------------------------------------
__global__ void init_kernel(const float* __restrict__ bias, float* __restrict__ out, int n) {
    int idx = blockIdx.x * blockDim.x + threadIdx.x;
    int total = n * 64;  // float4 units over out
    if (idx < total) {
        const float4* b4 = (const float4*)bias;
        ((float4*)out)[idx] = b4[idx & 63];
    }
    if (idx < n) g_cnt[idx] = 0;
}

// ---------------------------------------------------------------------------
// 2. Count in-degrees
// ---------------------------------------------------------------------------
__global__ void count_kernel(const void* __restrict__ ei, int E) {
    int e = blockIdx.x * blockDim.x + threadIdx.x;
    if (e >= E) return;
    long long d = load_edge(ei, g_is64, (size_t)E + e);
    atomicAdd(&g_cnt[(int)d], 1);
}

// ---------------------------------------------------------------------------
// 3. Exclusive scan of counts -> offsets (+ cursor copy). Single block, 1024 thr.
// ---------------------------------------------------------------------------
__global__ void scan_kernel(int N) {
    __shared__ int tmp[1024];
    int t = threadIdx.x;
    int chunk = (N + 1023) / 1024;
    int beg = t * chunk;
    int end = min(beg + chunk, N);

    int s = 0;
    for (int i = beg; i < end; i++) s += g_cnt[i];
    tmp[t] = s;
    __syncthreads();

    // Hillis-Steele inclusive scan over 1024 partial sums
    for (int off = 1; off < 1024; off <<= 1) {
        int v = (t >= off) ? tmp[t - off] : 0;
        __syncthreads();
        tmp[t] += v;
        __syncthreads();
    }

    int prefix = (t == 0) ? 0 : tmp[t - 1];  // exclusive prefix of this chunk
    for (int i = beg; i < end; i++) {
        int c = g_cnt[i];
        g_off[i] = prefix;
        g_cur[i] = prefix;
        prefix += c;
    }
    if (t == 1023) g_off[N] = tmp[1023];
}

// ---------------------------------------------------------------------------
// 4. Scatter src ids into CSR slots
// ---------------------------------------------------------------------------
__global__ void scatter_kernel(const void* __restrict__ ei, int E) {
    int e = blockIdx.x * blockDim.x + threadIdx.x;
    if (e >= E) return;
    int is64 = g_is64;
    long long s = load_edge(ei, is64, e);
    long long d = load_edge(ei, is64, (size_t)E + e);
    int pos = atomicAdd(&g_cur[(int)d], 1);
    g_srclist[pos] = (int)s;
}

// ---------------------------------------------------------------------------
// 5. GEMM: xl[n, 256] = x[n, 64] @ W[64, 256]
// ---------------------------------------------------------------------------
__global__ void gemm_kernel(const float* __restrict__ x, const float* __restrict__ W, int n) {
    extern __shared__ float sm[];
    float* sW = sm;              // 64*256 floats
    float* sX = sm + 64 * 256;   // 64 rows * 65 (padded)

    int t = threadIdx.x;
    int row0 = blockIdx.x * 64;

    const float4* W4 = (const float4*)W;
    float4* sW4 = (float4*)sW;
#pragma unroll
    for (int i = 0; i < 16; i++) sW4[t + i * 256] = W4[t + i * 256];

#pragma unroll
    for (int i = 0; i < 16; i++) {
        int idx = t + i * 256;
        int r = idx >> 6, c = idx & 63;
        float v = (row0 + r < n) ? x[(size_t)(row0 + r) * D_IN + c] : 0.f;
        sX[r * 65 + c] = v;
    }
    __syncthreads();

    int tr = t >> 4;
    int tc = t & 15;

    float acc[4][16];
#pragma unroll
    for (int j = 0; j < 4; j++)
#pragma unroll
        for (int i = 0; i < 16; i++) acc[j][i] = 0.f;

#pragma unroll 4
    for (int k = 0; k < 64; k++) {
        float xv[4];
#pragma unroll
        for (int j = 0; j < 4; j++) xv[j] = sX[(tr * 4 + j) * 65 + k];
#pragma unroll
        for (int q = 0; q < 4; q++) {
            float4 w = *(const float4*)(sW + k * 256 + q * 64 + tc * 4);
#pragma unroll
            for (int j = 0; j < 4; j++) {
                acc[j][q * 4 + 0] += xv[j] * w.x;
                acc[j][q * 4 + 1] += xv[j] * w.y;
                acc[j][q * 4 + 2] += xv[j] * w.z;
                acc[j][q * 4 + 3] += xv[j] * w.w;
            }
        }
    }

#pragma unroll
    for (int j = 0; j < 4; j++) {
        int r = row0 + tr * 4 + j;
        if (r < n) {
#pragma unroll
            for (int q = 0; q < 4; q++) {
                float4 v = make_float4(acc[j][q * 4 + 0], acc[j][q * 4 + 1],
                                       acc[j][q * 4 + 2], acc[j][q * 4 + 3]);
                *(float4*)(g_xl + (size_t)r * HC + q * 64 + tc * 4) = v;
            }
        }
    }
}

// ---------------------------------------------------------------------------
// 6. Attention scores: a_src[n,h] = <xl[n,h,:], att_src[h,:]>, same for dst.
// ---------------------------------------------------------------------------
__global__ void att_kernel(const float* __restrict__ att_src,
                           const float* __restrict__ att_dst, int n) {
    int w = (blockIdx.x * blockDim.x + threadIdx.x) >> 5;
    int lane = threadIdx.x & 31;
    if (w >= n) return;
    int h = lane >> 3;
    int c = lane * 8;

    const float* xr = g_xl + (size_t)w * HC + c;
    float4 v0 = *(const float4*)xr;
    float4 v1 = *(const float4*)(xr + 4);
    const float* as = att_src + c;
    const float* ad = att_dst + c;
    float4 s0 = *(const float4*)as, s1 = *(const float4*)(as + 4);
    float4 d0 = *(const float4*)ad, d1 = *(const float4*)(ad + 4);

    float ps = v0.x * s0.x + v0.y * s0.y + v0.z * s0.z + v0.w * s0.w
             + v1.x * s1.x + v1.y * s1.y + v1.z * s1.z + v1.w * s1.w;
    float pd = v0.x * d0.x + v0.y * d0.y + v0.z * d0.z + v0.w * d0.w
             + v1.x * d1.x + v1.y * d1.y + v1.z * d1.z + v1.w * d1.w;

#pragma unroll
    for (int off = 4; off > 0; off >>= 1) {
        ps += __shfl_down_sync(0xffffffff, ps, off);
        pd += __shfl_down_sync(0xffffffff, pd, off);
    }
    if ((lane & 7) == 0) {
        g_asrc[w * HEADS + h] = ps;
        g_adst[w * HEADS + h] = pd;
    }
}

// ---------------------------------------------------------------------------
// 7. Aggregate, warp per destination node, online softmax.
//    lane handles channels [lane*8, lane*8+8), head h = lane>>3.
// ---------------------------------------------------------------------------
__global__ void agg_kernel(const float* __restrict__ bias, float* __restrict__ out, int N) {
    int w = (blockIdx.x * blockDim.x + threadIdx.x) >> 5;
    int lane = threadIdx.x & 31;
    if (w >= N) return;

    int beg = g_off[w];
    int end = g_off[w + 1];
    if (beg == end) return;  // out stays at bias (init)

    int h = lane >> 3;
    float adh = g_adst[w * HEADS + h];

    float m = -FLT_MAX;
    float den = 0.f;
    float acc[8];
#pragma unroll
    for (int k = 0; k < 8; k++) acc[k] = 0.f;

    for (int i = beg; i < end; i++) {
        int s = g_srclist[i];
        float l = g_asrc[s * HEADS + h] + adh;
        l = (l >= 0.f) ? l : 0.2f * l;

        float m_new = fmaxf(m, l);
        float scale = __expf(m - m_new);     // 1 if no new max; 0 on first iter
        float we = __expf(l - m_new);
        den = den * scale + we;

        const float4* xs = (const float4*)(g_xl + (size_t)s * HC + lane * 8);
        float4 v0 = xs[0], v1 = xs[1];
        acc[0] = acc[0] * scale + we * v0.x;
        acc[1] = acc[1] * scale + we * v0.y;
        acc[2] = acc[2] * scale + we * v0.z;
        acc[3] = acc[3] * scale + we * v0.w;
        acc[4] = acc[4] * scale + we * v1.x;
        acc[5] = acc[5] * scale + we * v1.y;
        acc[6] = acc[6] * scale + we * v1.z;
        acc[7] = acc[7] * scale + we * v1.w;
        m = m_new;
    }

    float inv = 1.f / (den + 1e-16f);
    const float* bp = bias + lane * 8;
    float4 b0 = *(const float4*)bp;
    float4 b1 = *(const float4*)(bp + 4);
    float4 o0 = make_float4(acc[0] * inv + b0.x, acc[1] * inv + b0.y,
                            acc[2] * inv + b0.z, acc[3] * inv + b0.w);
    float4 o1 = make_float4(acc[4] * inv + b1.x, acc[5] * inv + b1.y,
                            acc[6] * inv + b1.z, acc[7] * inv + b1.w);
    float* po = out + (size_t)w * HC + lane * 8;
    *(float4*)po = o0;
    *(float4*)(po + 4) = o1;
}

// ---------------------------------------------------------------------------
// Launch
// ---------------------------------------------------------------------------
extern "C" void kernel_launch(void* const* d_in, const int* in_sizes, int n_in,
                              void* d_out, int out_size) {
    const float* x        = (const float*)d_in[0];
    const void*  ei       = (const void*)d_in[1];
    const float* W        = (const float*)d_in[2];
    const float* att_src  = (const float*)d_in[3];
    const float* att_dst  = (const float*)d_in[4];
    const float* bias     = (const float*)d_in[5];
    float* out = (float*)d_out;

    int N = in_sizes[0] / D_IN;
    int E = in_sizes[1] / 2;

    detect_kernel<<<1, 1>>>(ei);

    int init_threads = N * 64;
    init_kernel<<<(init_threads + 255) / 256, 256>>>(bias, out, N);

    count_kernel<<<(E + 255) / 256, 256>>>(ei, E);
    scan_kernel<<<1, 1024>>>(N);
    scatter_kernel<<<(E + 255) / 256, 256>>>(ei, E);

    size_t smem = (size_t)64 * 256 * 4 + (size_t)64 * 65 * 4;  // 82176 B
    cudaFuncSetAttribute(gemm_kernel, cudaFuncAttributeMaxDynamicSharedMemorySize, (int)smem);
    gemm_kernel<<<(N + 63) / 64, 256, smem>>>(x, W, N);

    att_kernel<<<(N * 32 + 255) / 256, 256>>>(att_src, att_dst, N);

    long long agg_threads = (long long)N * 32;
    agg_kernel<<<(int)((agg_threads + 255) / 256), 256>>>(bias, out, N);
}

// round 3
// speedup vs baseline: 2.5514x; 1.5325x over previous
#include <cuda_runtime.h>
#include <math.h>
#include <float.h>
#include <stdint.h>

// Problem constants (GAT_38585986187787)
#define MAX_NODES 100000
#define MAX_EDGES 1600000
#define D_IN 64
#define HEADS 4
#define HC 256   // HEADS * C_OUT
#define SCAN_B 1024
#define MAX_SCAN_BLOCKS 128

// ---------------------------------------------------------------------------
// Device scratch
// ---------------------------------------------------------------------------
__device__ float g_xl[(size_t)MAX_NODES * HC];      // 102.4 MB   x @ W
__device__ float g_asrc[MAX_NODES * HEADS];         // 1.6 MB
__device__ float g_adst[MAX_NODES * HEADS];         // 1.6 MB
__device__ int   g_cnt[MAX_NODES];                  // in-degree counts
__device__ int   g_off[MAX_NODES + 1];              // CSR offsets (by dst)
__device__ int   g_cur[MAX_NODES];                  // scatter cursors
__device__ int   g_srclist[MAX_EDGES];              // src id per CSR slot
__device__ int   g_bsum[MAX_SCAN_BLOCKS];           // scan block sums
__device__ int   g_bpre[MAX_SCAN_BLOCKS];           // scan block prefixes
__device__ int   g_is64;                            // edge_index dtype flag

__device__ __forceinline__ long long load_edge(const void* ei, int is64, size_t idx) {
    if (is64) return ((const long long*)ei)[idx];
    return (long long)(((const int*)ei)[idx]);
}

// ---------------------------------------------------------------------------
// 0. Detect edge_index dtype (int64 vs silently-downcast int32)
// ---------------------------------------------------------------------------
__global__ void detect_kernel(const void* ei) {
    const unsigned long long* p = (const unsigned long long*)ei;
    bool ok = true;
#pragma unroll
    for (int i = 0; i < 16; i++) ok = ok && (p[i] < (unsigned long long)MAX_NODES);
    g_is64 = ok ? 1 : 0;
}

// ---------------------------------------------------------------------------
// 1. Init: out = bias broadcast (covers deg-0 nodes), zero degree counters
// ---------------------------------------------------------------------------
__global__ void init_kernel(const float* __restrict__ bias, float* __restrict__ out, int n) {
    int idx = blockIdx.x * blockDim.x + threadIdx.x;
    int total = n * 64;  // float4 units over out
    if (idx < total) {
        const float4* b4 = (const float4*)bias;
        ((float4*)out)[idx] = b4[idx & 63];
    }
    if (idx < n) g_cnt[idx] = 0;
}

// ---------------------------------------------------------------------------
// 2. Count in-degrees
// ---------------------------------------------------------------------------
__global__ void count_kernel(const void* __restrict__ ei, int E) {
    int e = blockIdx.x * blockDim.x + threadIdx.x;
    if (e >= E) return;
    long long d = load_edge(ei, g_is64, (size_t)E + e);
    atomicAdd(&g_cnt[(int)d], 1);
}

// ---------------------------------------------------------------------------
// 3a. Block-local exclusive scan (shfl-based), block sums to g_bsum
// ---------------------------------------------------------------------------
__global__ void scan1_kernel(int N) {
    int t = threadIdx.x;
    int i = blockIdx.x * SCAN_B + t;
    int lane = t & 31, wid = t >> 5;

    int v = (i < N) ? g_cnt[i] : 0;
    int x = v;
#pragma unroll
    for (int off = 1; off < 32; off <<= 1) {
        int u = __shfl_up_sync(0xffffffffu, x, off);
        if (lane >= off) x += u;
    }
    __shared__ int wsum[32];
    if (lane == 31) wsum[wid] = x;
    __syncthreads();
    if (wid == 0) {
        int y = wsum[lane];
#pragma unroll
        for (int off = 1; off < 32; off <<= 1) {
            int u = __shfl_up_sync(0xffffffffu, y, off);
            if (lane >= off) y += u;
        }
        wsum[lane] = y;
    }
    __syncthreads();
    int base = (wid > 0) ? wsum[wid - 1] : 0;
    int incl = base + x;
    if (i < N) g_off[i] = incl - v;           // local exclusive, no block base yet
    if (t == SCAN_B - 1) g_bsum[blockIdx.x] = incl;
}

// ---------------------------------------------------------------------------
// 3b. Scan the block sums (nb <= 128), one block of 128 threads
// ---------------------------------------------------------------------------
__global__ void scan2_kernel(int nb, int N, int E) {
    int t = threadIdx.x, lane = t & 31, wid = t >> 5;
    int v = (t < nb) ? g_bsum[t] : 0;
    int x = v;
#pragma unroll
    for (int off = 1; off < 32; off <<= 1) {
        int u = __shfl_up_sync(0xffffffffu, x, off);
        if (lane >= off) x += u;
    }
    __shared__ int ws[4];
    __shared__ int wpre[4];
    if (lane == 31) ws[wid] = x;
    __syncthreads();
    if (t == 0) {
        int s = 0;
#pragma unroll
        for (int k = 0; k < 4; k++) { wpre[k] = s; s += ws[k]; }
    }
    __syncthreads();
    int incl = wpre[wid] + x;
    if (t < nb) g_bpre[t] = incl - v;
    if (t == 0) g_off[N] = E;
}

// ---------------------------------------------------------------------------
// 3c. Add block bases, emit cursors
// ---------------------------------------------------------------------------
__global__ void scan3_kernel(int N) {
    int i = blockIdx.x * SCAN_B + threadIdx.x;
    if (i < N) {
        int o = g_off[i] + g_bpre[blockIdx.x];
        g_off[i] = o;
        g_cur[i] = o;
    }
}

// ---------------------------------------------------------------------------
// 4. Scatter src ids into CSR slots
// ---------------------------------------------------------------------------
__global__ void scatter_kernel(const void* __restrict__ ei, int E) {
    int e = blockIdx.x * blockDim.x + threadIdx.x;
    if (e >= E) return;
    int is64 = g_is64;
    long long s = load_edge(ei, is64, e);
    long long d = load_edge(ei, is64, (size_t)E + e);
    int pos = atomicAdd(&g_cur[(int)d], 1);
    g_srclist[pos] = (int)s;
}

// ---------------------------------------------------------------------------
// 5. GEMM + fused attention scores.
//    xl[n,256] = x[n,64] @ W[64,256];
//    a_src[n,h] = <xl[n,h,:], att_src[h,:]>, a_dst likewise — computed from
//    in-register accumulators (cols q*64+tc*4+k partition by head q).
// ---------------------------------------------------------------------------
__global__ void gemm_kernel(const float* __restrict__ x, const float* __restrict__ W,
                            const float* __restrict__ att_src,
                            const float* __restrict__ att_dst, int n) {
    extern __shared__ float sm[];
    float* sW = sm;              // 64*256 floats
    float* sX = sm + 64 * 256;   // 64 rows * 65 (padded)

    int t = threadIdx.x;
    int row0 = blockIdx.x * 64;

    const float4* W4 = (const float4*)W;
    float4* sW4 = (float4*)sW;
#pragma unroll
    for (int i = 0; i < 16; i++) sW4[t + i * 256] = W4[t + i * 256];

#pragma unroll
    for (int i = 0; i < 16; i++) {
        int idx = t + i * 256;
        int r = idx >> 6, c = idx & 63;
        float v = (row0 + r < n) ? x[(size_t)(row0 + r) * D_IN + c] : 0.f;
        sX[r * 65 + c] = v;
    }
    __syncthreads();

    int tr = t >> 4;
    int tc = t & 15;

    float acc[4][16];
#pragma unroll
    for (int j = 0; j < 4; j++)
#pragma unroll
        for (int i = 0; i < 16; i++) acc[j][i] = 0.f;

#pragma unroll 4
    for (int k = 0; k < 64; k++) {
        float xv[4];
#pragma unroll
        for (int j = 0; j < 4; j++) xv[j] = sX[(tr * 4 + j) * 65 + k];
#pragma unroll
        for (int q = 0; q < 4; q++) {
            float4 w = *(const float4*)(sW + k * 256 + q * 64 + tc * 4);
#pragma unroll
            for (int j = 0; j < 4; j++) {
                acc[j][q * 4 + 0] += xv[j] * w.x;
                acc[j][q * 4 + 1] += xv[j] * w.y;
                acc[j][q * 4 + 2] += xv[j] * w.z;
                acc[j][q * 4 + 3] += xv[j] * w.w;
            }
        }
    }

    // Store xl
#pragma unroll
    for (int j = 0; j < 4; j++) {
        int r = row0 + tr * 4 + j;
        if (r < n) {
#pragma unroll
            for (int q = 0; q < 4; q++) {
                float4 v = make_float4(acc[j][q * 4 + 0], acc[j][q * 4 + 1],
                                       acc[j][q * 4 + 2], acc[j][q * 4 + 3]);
                *(float4*)(g_xl + (size_t)r * HC + q * 64 + tc * 4) = v;
            }
        }
    }

    // Fused attention scores: per (row j, head q), reduce partial dots over tc.
    float4 As[4], Ad[4];
#pragma unroll
    for (int q = 0; q < 4; q++) {
        As[q] = ((const float4*)att_src)[q * 16 + tc];
        Ad[q] = ((const float4*)att_dst)[q * 16 + tc];
    }
#pragma unroll
    for (int j = 0; j < 4; j++) {
#pragma unroll
        for (int q = 0; q < 4; q++) {
            float ps = acc[j][q * 4 + 0] * As[q].x + acc[j][q * 4 + 1] * As[q].y
                     + acc[j][q * 4 + 2] * As[q].z + acc[j][q * 4 + 3] * As[q].w;
            float pd = acc[j][q * 4 + 0] * Ad[q].x + acc[j][q * 4 + 1] * Ad[q].y
                     + acc[j][q * 4 + 2] * Ad[q].z + acc[j][q * 4 + 3] * Ad[q].w;
#pragma unroll
            for (int off = 8; off > 0; off >>= 1) {
                ps += __shfl_down_sync(0xffffffffu, ps, off, 16);
                pd += __shfl_down_sync(0xffffffffu, pd, off, 16);
            }
            if (tc == 0) {
                int r = row0 + tr * 4 + j;
                if (r < n) {
                    g_asrc[r * HEADS + q] = ps;
                    g_adst[r * HEADS + q] = pd;
                }
            }
        }
    }
}

// ---------------------------------------------------------------------------
// 6. Aggregate, warp per destination node, online softmax, pipelined.
//    lane handles channels [lane*8, lane*8+8), head h = lane>>3.
// ---------------------------------------------------------------------------
__global__ void agg_kernel(const float* __restrict__ bias, float* __restrict__ out, int N) {
    int w = (blockIdx.x * blockDim.x + threadIdx.x) >> 5;
    int lane = threadIdx.x & 31;
    if (w >= N) return;

    int beg = g_off[w];
    int end = g_off[w + 1];
    if (beg == end) return;  // out stays at bias (init)

    int h = lane >> 3;
    float adh = g_adst[w * HEADS + h];

    float m = -FLT_MAX;
    float den = 0.f;
    float acc[8];
#pragma unroll
    for (int k = 0; k < 8; k++) acc[k] = 0.f;

    // Software pipeline: prefetch next src id + src score.
    int s_nxt = g_srclist[beg];
    float a_nxt = g_asrc[s_nxt * HEADS + h];

    for (int i = beg; i < end; i++) {
        int s = s_nxt;
        float a = a_nxt;
        if (i + 1 < end) {
            s_nxt = g_srclist[i + 1];
            a_nxt = g_asrc[s_nxt * HEADS + h];
        }

        float l = a + adh;
        l = (l >= 0.f) ? l : 0.2f * l;

        float m_new = fmaxf(m, l);
        float scale = __expf(m - m_new);     // 1 if no new max; 0 on first iter
        float we = __expf(l - m_new);
        den = den * scale + we;

        const float4* xs = (const float4*)(g_xl + (size_t)s * HC + lane * 8);
        float4 v0 = xs[0], v1 = xs[1];
        acc[0] = acc[0] * scale + we * v0.x;
        acc[1] = acc[1] * scale + we * v0.y;
        acc[2] = acc[2] * scale + we * v0.z;
        acc[3] = acc[3] * scale + we * v0.w;
        acc[4] = acc[4] * scale + we * v1.x;
        acc[5] = acc[5] * scale + we * v1.y;
        acc[6] = acc[6] * scale + we * v1.z;
        acc[7] = acc[7] * scale + we * v1.w;
        m = m_new;
    }

    float inv = 1.f / (den + 1e-16f);
    const float* bp = bias + lane * 8;
    float4 b0 = *(const float4*)bp;
    float4 b1 = *(const float4*)(bp + 4);
    float4 o0 = make_float4(acc[0] * inv + b0.x, acc[1] * inv + b0.y,
                            acc[2] * inv + b0.z, acc[3] * inv + b0.w);
    float4 o1 = make_float4(acc[4] * inv + b1.x, acc[5] * inv + b1.y,
                            acc[6] * inv + b1.z, acc[7] * inv + b1.w);
    float* po = out + (size_t)w * HC + lane * 8;
    *(float4*)po = o0;
    *(float4*)(po + 4) = o1;
}

// ---------------------------------------------------------------------------
// Launch
// ---------------------------------------------------------------------------
extern "C" void kernel_launch(void* const* d_in, const int* in_sizes, int n_in,
                              void* d_out, int out_size) {
    const float* x        = (const float*)d_in[0];
    const void*  ei       = (const void*)d_in[1];
    const float* W        = (const float*)d_in[2];
    const float* att_src  = (const float*)d_in[3];
    const float* att_dst  = (const float*)d_in[4];
    const float* bias     = (const float*)d_in[5];
    float* out = (float*)d_out;

    int N = in_sizes[0] / D_IN;
    int E = in_sizes[1] / 2;

    detect_kernel<<<1, 1>>>(ei);

    int init_threads = N * 64;
    init_kernel<<<(init_threads + 255) / 256, 256>>>(bias, out, N);

    count_kernel<<<(E + 255) / 256, 256>>>(ei, E);

    int nb = (N + SCAN_B - 1) / SCAN_B;   // 98 for N=100000
    scan1_kernel<<<nb, SCAN_B>>>(N);
    scan2_kernel<<<1, 128>>>(nb, N, E);
    scan3_kernel<<<nb, SCAN_B>>>(N);

    scatter_kernel<<<(E + 255) / 256, 256>>>(ei, E);

    size_t smem = (size_t)64 * 256 * 4 + (size_t)64 * 65 * 4;  // 82176 B
    cudaFuncSetAttribute(gemm_kernel, cudaFuncAttributeMaxDynamicSharedMemorySize, (int)smem);
    gemm_kernel<<<(N + 63) / 64, 256, smem>>>(x, W, att_src, att_dst, N);

    long long agg_threads = (long long)N * 32;
    agg_kernel<<<(int)((agg_threads + 255) / 256), 256>>>(bias, out, N);
}

// round 4
// speedup vs baseline: 2.9706x; 1.1643x over previous
#include <cuda_runtime.h>
#include <math.h>
#include <float.h>
#include <stdint.h>

// Problem constants (GAT_38585986187787)
#define MAX_NODES 100000
#define MAX_EDGES 1600000
#define D_IN 64
#define HEADS 4
#define HC 256   // HEADS * C_OUT
#define SCAN_B 1024
#define MAX_SCAN_BLOCKS 128

// smem strides (bank-conflict-free fragment loads)
#define SX_STR 68    // 68 % 32 == 4  -> bank = 4*row + k, distinct for 8x4 lanes
#define SW_STR 264   // 264 % 32 == 8 -> bank = 8*k + n,  distinct for 4x8 lanes

// ---------------------------------------------------------------------------
// Device scratch
// ---------------------------------------------------------------------------
__device__ float g_xl[(size_t)MAX_NODES * HC];      // 102.4 MB   x @ W
__device__ float g_asrc[MAX_NODES * HEADS];         // 1.6 MB
__device__ float g_adst[MAX_NODES * HEADS];         // 1.6 MB
__device__ int   g_cnt[MAX_NODES];                  // in-degree counts
__device__ int   g_off[MAX_NODES + 1];              // CSR offsets (by dst)
__device__ int   g_cur[MAX_NODES];                  // scatter cursors
__device__ int   g_srclist[MAX_EDGES];              // src id per CSR slot
__device__ int   g_bsum[MAX_SCAN_BLOCKS];           // scan block sums
__device__ int   g_bpre[MAX_SCAN_BLOCKS];           // scan block prefixes
__device__ int   g_is64;                            // edge_index dtype flag

__device__ __forceinline__ long long load_edge(const void* ei, int is64, size_t idx) {
    if (is64) return ((const long long*)ei)[idx];
    return (long long)(((const int*)ei)[idx]);
}

__device__ __forceinline__ uint32_t f2tf32(float f) {
    uint32_t r;
    asm("cvt.rna.tf32.f32 %0, %1;" : "=r"(r) : "f"(f));
    return r;
}

// ---------------------------------------------------------------------------
// 0. Detect edge_index dtype (int64 vs silently-downcast int32)
// ---------------------------------------------------------------------------
__global__ void detect_kernel(const void* ei) {
    const unsigned long long* p = (const unsigned long long*)ei;
    bool ok = true;
#pragma unroll
    for (int i = 0; i < 16; i++) ok = ok && (p[i] < (unsigned long long)MAX_NODES);
    g_is64 = ok ? 1 : 0;
}

// ---------------------------------------------------------------------------
// 1. Init: zero degree counters only (agg writes every out row itself)
// ---------------------------------------------------------------------------
__global__ void init_kernel(int n) {
    int idx = blockIdx.x * blockDim.x + threadIdx.x;
    if (idx < n) g_cnt[idx] = 0;
}

// ---------------------------------------------------------------------------
// 2. Count in-degrees
// ---------------------------------------------------------------------------
__global__ void count_kernel(const void* __restrict__ ei, int E) {
    int e = blockIdx.x * blockDim.x + threadIdx.x;
    if (e >= E) return;
    long long d = load_edge(ei, g_is64, (size_t)E + e);
    atomicAdd(&g_cnt[(int)d], 1);
}

// ---------------------------------------------------------------------------
// 3a. Block-local exclusive scan (shfl-based), block sums to g_bsum
// ---------------------------------------------------------------------------
__global__ void scan1_kernel(int N) {
    int t = threadIdx.x;
    int i = blockIdx.x * SCAN_B + t;
    int lane = t & 31, wid = t >> 5;

    int v = (i < N) ? g_cnt[i] : 0;
    int x = v;
#pragma unroll
    for (int off = 1; off < 32; off <<= 1) {
        int u = __shfl_up_sync(0xffffffffu, x, off);
        if (lane >= off) x += u;
    }
    __shared__ int wsum[32];
    if (lane == 31) wsum[wid] = x;
    __syncthreads();
    if (wid == 0) {
        int y = wsum[lane];
#pragma unroll
        for (int off = 1; off < 32; off <<= 1) {
            int u = __shfl_up_sync(0xffffffffu, y, off);
            if (lane >= off) y += u;
        }
        wsum[lane] = y;
    }
    __syncthreads();
    int base = (wid > 0) ? wsum[wid - 1] : 0;
    int incl = base + x;
    if (i < N) g_off[i] = incl - v;           // local exclusive, no block base yet
    if (t == SCAN_B - 1) g_bsum[blockIdx.x] = incl;
}

// ---------------------------------------------------------------------------
// 3b. Scan the block sums (nb <= 128), one block of 128 threads
// ---------------------------------------------------------------------------
__global__ void scan2_kernel(int nb, int N, int E) {
    int t = threadIdx.x, lane = t & 31, wid = t >> 5;
    int v = (t < nb) ? g_bsum[t] : 0;
    int x = v;
#pragma unroll
    for (int off = 1; off < 32; off <<= 1) {
        int u = __shfl_up_sync(0xffffffffu, x, off);
        if (lane >= off) x += u;
    }
    __shared__ int ws[4];
    __shared__ int wpre[4];
    if (lane == 31) ws[wid] = x;
    __syncthreads();
    if (t == 0) {
        int s = 0;
#pragma unroll
        for (int k = 0; k < 4; k++) { wpre[k] = s; s += ws[k]; }
    }
    __syncthreads();
    int incl = wpre[wid] + x;
    if (t < nb) g_bpre[t] = incl - v;
    if (t == 0) g_off[N] = E;
}

// ---------------------------------------------------------------------------
// 3c. Add block bases, emit cursors
// ---------------------------------------------------------------------------
__global__ void scan3_kernel(int N) {
    int i = blockIdx.x * SCAN_B + threadIdx.x;
    if (i < N) {
        int o = g_off[i] + g_bpre[blockIdx.x];
        g_off[i] = o;
        g_cur[i] = o;
    }
}

// ---------------------------------------------------------------------------
// 4. Scatter src ids into CSR slots
// ---------------------------------------------------------------------------
__global__ void scatter_kernel(const void* __restrict__ ei, int E) {
    int e = blockIdx.x * blockDim.x + threadIdx.x;
    if (e >= E) return;
    int is64 = g_is64;
    long long s = load_edge(ei, is64, e);
    long long d = load_edge(ei, is64, (size_t)E + e);
    int pos = atomicAdd(&g_cur[(int)d], 1);
    g_srclist[pos] = (int)s;
}

// ---------------------------------------------------------------------------
// 5. TF32 tensor-core GEMM + fused attention scores.
//    Block: 256 thr (8 warps), tile M=64, N=256, K=64.
//    Warp grid 2(M) x 4(N): warp tile 32x64 -> warp wn owns head wn entirely.
//    mma.sync.m16n8k8 tf32: per warp 2 mtiles x 8 ntiles, 8 k-chunks.
// ---------------------------------------------------------------------------
__global__ void __launch_bounds__(256, 2)
gemm_kernel(const float* __restrict__ x, const float* __restrict__ W,
            const float* __restrict__ att_src,
            const float* __restrict__ att_dst, int n) {
    extern __shared__ uint32_t sm[];
    uint32_t* sX = sm;                    // 64 x SX_STR
    uint32_t* sW = sm + 64 * SX_STR;      // 64 x SW_STR

    int t = threadIdx.x;
    int lane = t & 31;
    int wid = t >> 5;
    int wm = wid >> 2;        // 0..1   (M group: rows wm*32 .. +32)
    int wn = wid & 3;         // 0..3   (N group / head: cols wn*64 .. +64)
    int row0 = blockIdx.x * 64;

    // ---- Stage x tile (64x64) as tf32, stride SX_STR ----
    // 4096 elems / 256 thr = 16 each (4 x float4)
#pragma unroll
    for (int i = 0; i < 4; i++) {
        int idx4 = t + i * 256;           // float4 index; row = idx4/16, c4 = idx4%16
        int r = idx4 >> 4, c = (idx4 & 15) * 4;
        float4 v = make_float4(0.f, 0.f, 0.f, 0.f);
        if (row0 + r < n) v = *(const float4*)(x + (size_t)(row0 + r) * D_IN + c);
        uint32_t* p = sX + r * SX_STR + c;
        p[0] = f2tf32(v.x); p[1] = f2tf32(v.y); p[2] = f2tf32(v.z); p[3] = f2tf32(v.w);
    }

    // ---- Stage W (64x256) as tf32, stride SW_STR ----
    // 16384 elems / 256 thr = 64 each (16 x float4)
#pragma unroll
    for (int i = 0; i < 16; i++) {
        int idx4 = t + i * 256;           // float4 index; row = idx4/64, c4 = idx4%64
        int r = idx4 >> 6, c = (idx4 & 63) * 4;
        float4 v = *(const float4*)(W + (size_t)r * HC + c);
        uint32_t* p = sW + r * SW_STR + c;
        p[0] = f2tf32(v.x); p[1] = f2tf32(v.y); p[2] = f2tf32(v.z); p[3] = f2tf32(v.w);
    }
    __syncthreads();

    // ---- MMA mainloop ----
    // acc[mtile][ntile][4]
    float acc[2][8][4];
#pragma unroll
    for (int mt = 0; mt < 2; mt++)
#pragma unroll
        for (int nt = 0; nt < 8; nt++)
#pragma unroll
            for (int k = 0; k < 4; k++) acc[mt][nt][k] = 0.f;

    int qr = lane >> 2;   // 0..7  (quad row)
    int ql = lane & 3;    // 0..3  (quad lane)

#pragma unroll
    for (int kc = 0; kc < 8; kc++) {
        int k0 = kc * 8;
        // A fragments: a[mt][0..3]; A row-major 16x8
        uint32_t a[2][4];
#pragma unroll
        for (int mt = 0; mt < 2; mt++) {
            int rbase = wm * 32 + mt * 16 + qr;
            const uint32_t* pa = sX + rbase * SX_STR + k0 + ql;
            a[mt][0] = pa[0];
            a[mt][1] = pa[8 * SX_STR];
            a[mt][2] = pa[4];
            a[mt][3] = pa[8 * SX_STR + 4];
        }
        // B fragments: b[nt][0..1]; B col-major (k-major) 8x8
        uint32_t b[8][2];
#pragma unroll
        for (int nt = 0; nt < 8; nt++) {
            int nbase = wn * 64 + nt * 8 + qr;
            const uint32_t* pb = sW + (k0 + ql) * SW_STR + nbase;
            b[nt][0] = pb[0];
            b[nt][1] = pb[4 * SW_STR];
        }
#pragma unroll
        for (int mt = 0; mt < 2; mt++)
#pragma unroll
            for (int nt = 0; nt < 8; nt++) {
                float* c = acc[mt][nt];
                asm volatile(
                    "mma.sync.aligned.m16n8k8.row.col.f32.tf32.tf32.f32 "
                    "{%0,%1,%2,%3}, {%4,%5,%6,%7}, {%8,%9}, {%0,%1,%2,%3};"
                    : "+f"(c[0]), "+f"(c[1]), "+f"(c[2]), "+f"(c[3])
                    : "r"(a[mt][0]), "r"(a[mt][1]), "r"(a[mt][2]), "r"(a[mt][3]),
                      "r"(b[nt][0]), "r"(b[nt][1]));
            }
    }

    // ---- Store xl + fused attention dots ----
    // C frag: c0,c1 -> (row=qr, cols 2*ql, 2*ql+1); c2,c3 -> row=qr+8.
    float ps[4], pd[4];   // per local row instance: [mt*2 + (0: qr, 1: qr+8)]
#pragma unroll
    for (int k = 0; k < 4; k++) { ps[k] = 0.f; pd[k] = 0.f; }

#pragma unroll
    for (int mt = 0; mt < 2; mt++) {
        int r_lo = row0 + wm * 32 + mt * 16 + qr;
#pragma unroll
        for (int nt = 0; nt < 8; nt++) {
            int col = wn * 64 + nt * 8 + 2 * ql;      // global col
            int cl = nt * 8 + 2 * ql;                  // col within head
            const float* c = acc[mt][nt];
            // attention vectors for head wn
            float a0s = att_src[wn * 64 + cl], a1s = att_src[wn * 64 + cl + 1];
            float a0d = att_dst[wn * 64 + cl], a1d = att_dst[wn * 64 + cl + 1];
            ps[mt * 2 + 0] += c[0] * a0s + c[1] * a1s;
            pd[mt * 2 + 0] += c[0] * a0d + c[1] * a1d;
            ps[mt * 2 + 1] += c[2] * a0s + c[3] * a1s;
            pd[mt * 2 + 1] += c[2] * a0d + c[3] * a1d;
            if (r_lo < n)
                *(float2*)(g_xl + (size_t)r_lo * HC + col) = make_float2(c[0], c[1]);
            if (r_lo + 8 < n)
                *(float2*)(g_xl + (size_t)(r_lo + 8) * HC + col) = make_float2(c[2], c[3]);
        }
    }

    // Quad reduction (4 lanes share a row)
#pragma unroll
    for (int k = 0; k < 4; k++) {
#pragma unroll
        for (int off = 2; off > 0; off >>= 1) {
            ps[k] += __shfl_down_sync(0xffffffffu, ps[k], off, 4);
            pd[k] += __shfl_down_sync(0xffffffffu, pd[k], off, 4);
        }
    }
    if (ql == 0) {
#pragma unroll
        for (int mt = 0; mt < 2; mt++) {
            int r_lo = row0 + wm * 32 + mt * 16 + qr;
            if (r_lo < n) {
                g_asrc[r_lo * HEADS + wn] = ps[mt * 2 + 0];
                g_adst[r_lo * HEADS + wn] = pd[mt * 2 + 0];
            }
            if (r_lo + 8 < n) {
                g_asrc[(r_lo + 8) * HEADS + wn] = ps[mt * 2 + 1];
                g_adst[(r_lo + 8) * HEADS + wn] = pd[mt * 2 + 1];
            }
        }
    }
}

// ---------------------------------------------------------------------------
// 6. Aggregate, warp per destination node, online softmax, pipelined.
//    lane handles channels [lane*8, lane*8+8), head h = lane>>3.
//    Degree-0 nodes get bias (no separate init pass).
// ---------------------------------------------------------------------------
__global__ void agg_kernel(const float* __restrict__ bias, float* __restrict__ out, int N) {
    int w = (blockIdx.x * blockDim.x + threadIdx.x) >> 5;
    int lane = threadIdx.x & 31;
    if (w >= N) return;

    const float* bp = bias + lane * 8;
    float4 b0 = *(const float4*)bp;
    float4 b1 = *(const float4*)(bp + 4);
    float* po = out + (size_t)w * HC + lane * 8;

    int beg = g_off[w];
    int end = g_off[w + 1];
    if (beg == end) {
        *(float4*)po = b0;
        *(float4*)(po + 4) = b1;
        return;
    }

    int h = lane >> 3;
    float adh = g_adst[w * HEADS + h];

    float m = -FLT_MAX;
    float den = 0.f;
    float acc[8];
#pragma unroll
    for (int k = 0; k < 8; k++) acc[k] = 0.f;

    // Software pipeline: prefetch next src id + src score.
    int s_nxt = g_srclist[beg];
    float a_nxt = g_asrc[s_nxt * HEADS + h];

    for (int i = beg; i < end; i++) {
        int s = s_nxt;
        float a = a_nxt;
        if (i + 1 < end) {
            s_nxt = g_srclist[i + 1];
            a_nxt = g_asrc[s_nxt * HEADS + h];
        }

        float l = a + adh;
        l = (l >= 0.f) ? l : 0.2f * l;

        float m_new = fmaxf(m, l);
        float scale = __expf(m - m_new);     // 1 if no new max; 0 on first iter
        float we = __expf(l - m_new);
        den = den * scale + we;

        const float4* xs = (const float4*)(g_xl + (size_t)s * HC + lane * 8);
        float4 v0 = xs[0], v1 = xs[1];
        acc[0] = acc[0] * scale + we * v0.x;
        acc[1] = acc[1] * scale + we * v0.y;
        acc[2] = acc[2] * scale + we * v0.z;
        acc[3] = acc[3] * scale + we * v0.w;
        acc[4] = acc[4] * scale + we * v1.x;
        acc[5] = acc[5] * scale + we * v1.y;
        acc[6] = acc[6] * scale + we * v1.z;
        acc[7] = acc[7] * scale + we * v1.w;
        m = m_new;
    }

    float inv = 1.f / (den + 1e-16f);
    float4 o0 = make_float4(acc[0] * inv + b0.x, acc[1] * inv + b0.y,
                            acc[2] * inv + b0.z, acc[3] * inv + b0.w);
    float4 o1 = make_float4(acc[4] * inv + b1.x, acc[5] * inv + b1.y,
                            acc[6] * inv + b1.z, acc[7] * inv + b1.w);
    *(float4*)po = o0;
    *(float4*)(po + 4) = o1;
}

// ---------------------------------------------------------------------------
// Launch
// ---------------------------------------------------------------------------
extern "C" void kernel_launch(void* const* d_in, const int* in_sizes, int n_in,
                              void* d_out, int out_size) {
    const float* x        = (const float*)d_in[0];
    const void*  ei       = (const void*)d_in[1];
    const float* W        = (const float*)d_in[2];
    const float* att_src  = (const float*)d_in[3];
    const float* att_dst  = (const float*)d_in[4];
    const float* bias     = (const float*)d_in[5];
    float* out = (float*)d_out;

    int N = in_sizes[0] / D_IN;
    int E = in_sizes[1] / 2;

    detect_kernel<<<1, 1>>>(ei);
    init_kernel<<<(N + 255) / 256, 256>>>(N);
    count_kernel<<<(E + 255) / 256, 256>>>(ei, E);

    int nb = (N + SCAN_B - 1) / SCAN_B;   // 98 for N=100000
    scan1_kernel<<<nb, SCAN_B>>>(N);
    scan2_kernel<<<1, 128>>>(nb, N, E);
    scan3_kernel<<<nb, SCAN_B>>>(N);

    scatter_kernel<<<(E + 255) / 256, 256>>>(ei, E);

    size_t smem = ((size_t)64 * SX_STR + (size_t)64 * SW_STR) * 4;  // ~85 KB
    cudaFuncSetAttribute(gemm_kernel, cudaFuncAttributeMaxDynamicSharedMemorySize, (int)smem);
    gemm_kernel<<<(N + 63) / 64, 256, smem>>>(x, W, att_src, att_dst, N);

    long long agg_threads = (long long)N * 32;
    agg_kernel<<<(int)((agg_threads + 255) / 256), 256>>>(bias, out, N);
}

// round 5
// speedup vs baseline: 3.1095x; 1.0468x over previous
#include <cuda_runtime.h>
#include <cuda_fp16.h>
#include <math.h>
#include <float.h>
#include <stdint.h>

// Problem constants (GAT_38585986187787)
#define MAX_NODES 100000
#define MAX_EDGES 1600000
#define D_IN 64
#define HEADS 4
#define HC 256   // HEADS * C_OUT
#define SCAN_B 1024
#define MAX_SCAN_BLOCKS 128

// smem strides in uint32 units (bank-conflict-free fragment loads)
#define SX_STR 68    // 68 % 32 == 4  -> bank = 4*row + k, distinct for 8x4 lanes
#define SW_STR 264   // 264 % 32 == 8 -> bank = 8*k + n,  distinct for 4x8 lanes

// ---------------------------------------------------------------------------
// Device scratch
// ---------------------------------------------------------------------------
__device__ __half g_xlh[(size_t)MAX_NODES * HC];    // 51.2 MB   x @ W (fp16)
__device__ float g_asrc[MAX_NODES * HEADS];         // 1.6 MB
__device__ float g_adst[MAX_NODES * HEADS];         // 1.6 MB
__device__ int   g_cnt[MAX_NODES];                  // in-degree counts
__device__ int   g_off[MAX_NODES + 1];              // CSR offsets (by dst)
__device__ int   g_cur[MAX_NODES];                  // scatter cursors
__device__ int   g_srclist[MAX_EDGES];              // src id per CSR slot
__device__ int   g_bsum[MAX_SCAN_BLOCKS];           // scan block sums
__device__ int   g_bpre[MAX_SCAN_BLOCKS];           // scan block prefixes
__device__ int   g_is64;                            // edge_index dtype flag

__device__ __forceinline__ long long load_edge(const void* ei, int is64, size_t idx) {
    if (is64) return ((const long long*)ei)[idx];
    return (long long)(((const int*)ei)[idx]);
}

__device__ __forceinline__ uint32_t f2tf32(float f) {
    uint32_t r;
    asm("cvt.rna.tf32.f32 %0, %1;" : "=r"(r) : "f"(f));
    return r;
}

// ---------------------------------------------------------------------------
// 0. Detect edge_index dtype (int64 vs silently-downcast int32)
// ---------------------------------------------------------------------------
__global__ void detect_kernel(const void* ei) {
    const unsigned long long* p = (const unsigned long long*)ei;
    bool ok = true;
#pragma unroll
    for (int i = 0; i < 16; i++) ok = ok && (p[i] < (unsigned long long)MAX_NODES);
    g_is64 = ok ? 1 : 0;
}

// ---------------------------------------------------------------------------
// 1. Init: zero degree counters only (agg writes every out row itself)
// ---------------------------------------------------------------------------
__global__ void init_kernel(int n) {
    int idx = blockIdx.x * blockDim.x + threadIdx.x;
    if (idx < n) g_cnt[idx] = 0;
}

// ---------------------------------------------------------------------------
// 2. Count in-degrees
// ---------------------------------------------------------------------------
__global__ void count_kernel(const void* __restrict__ ei, int E) {
    int e = blockIdx.x * blockDim.x + threadIdx.x;
    if (e >= E) return;
    long long d = load_edge(ei, g_is64, (size_t)E + e);
    atomicAdd(&g_cnt[(int)d], 1);
}

// ---------------------------------------------------------------------------
// 3a. Block-local exclusive scan (shfl-based), block sums to g_bsum
// ---------------------------------------------------------------------------
__global__ void scan1_kernel(int N) {
    int t = threadIdx.x;
    int i = blockIdx.x * SCAN_B + t;
    int lane = t & 31, wid = t >> 5;

    int v = (i < N) ? g_cnt[i] : 0;
    int x = v;
#pragma unroll
    for (int off = 1; off < 32; off <<= 1) {
        int u = __shfl_up_sync(0xffffffffu, x, off);
        if (lane >= off) x += u;
    }
    __shared__ int wsum[32];
    if (lane == 31) wsum[wid] = x;
    __syncthreads();
    if (wid == 0) {
        int y = wsum[lane];
#pragma unroll
        for (int off = 1; off < 32; off <<= 1) {
            int u = __shfl_up_sync(0xffffffffu, y, off);
            if (lane >= off) y += u;
        }
        wsum[lane] = y;
    }
    __syncthreads();
    int base = (wid > 0) ? wsum[wid - 1] : 0;
    int incl = base + x;
    if (i < N) g_off[i] = incl - v;           // local exclusive, no block base yet
    if (t == SCAN_B - 1) g_bsum[blockIdx.x] = incl;
}

// ---------------------------------------------------------------------------
// 3b. Scan the block sums (nb <= 128), one block of 128 threads
// ---------------------------------------------------------------------------
__global__ void scan2_kernel(int nb, int N, int E) {
    int t = threadIdx.x, lane = t & 31, wid = t >> 5;
    int v = (t < nb) ? g_bsum[t] : 0;
    int x = v;
#pragma unroll
    for (int off = 1; off < 32; off <<= 1) {
        int u = __shfl_up_sync(0xffffffffu, x, off);
        if (lane >= off) x += u;
    }
    __shared__ int ws[4];
    __shared__ int wpre[4];
    if (lane == 31) ws[wid] = x;
    __syncthreads();
    if (t == 0) {
        int s = 0;
#pragma unroll
        for (int k = 0; k < 4; k++) { wpre[k] = s; s += ws[k]; }
    }
    __syncthreads();
    int incl = wpre[wid] + x;
    if (t < nb) g_bpre[t] = incl - v;
    if (t == 0) g_off[N] = E;
}

// ---------------------------------------------------------------------------
// 3c. Add block bases, emit cursors
// ---------------------------------------------------------------------------
__global__ void scan3_kernel(int N) {
    int i = blockIdx.x * SCAN_B + threadIdx.x;
    if (i < N) {
        int o = g_off[i] + g_bpre[blockIdx.x];
        g_off[i] = o;
        g_cur[i] = o;
    }
}

// ---------------------------------------------------------------------------
// 4. Scatter src ids into CSR slots
// ---------------------------------------------------------------------------
__global__ void scatter_kernel(const void* __restrict__ ei, int E) {
    int e = blockIdx.x * blockDim.x + threadIdx.x;
    if (e >= E) return;
    int is64 = g_is64;
    long long s = load_edge(ei, is64, e);
    long long d = load_edge(ei, is64, (size_t)E + e);
    int pos = atomicAdd(&g_cur[(int)d], 1);
    g_srclist[pos] = (int)s;
}

// ---------------------------------------------------------------------------
// 5. TF32 tensor-core GEMM with residual correction + fused attention scores.
//    acc = Ah*Bh + Ah*Bl + Al*Bh  (tf32 error ~1e-6 instead of ~5e-4).
//    Block: 256 thr (8 warps), tile M=64, N=256, K=64.
//    Warp grid 2(M) x 4(N): warp wn owns head wn entirely.
//    xl stored to global as fp16.
// ---------------------------------------------------------------------------
__global__ void __launch_bounds__(256, 1)
gemm_kernel(const float* __restrict__ x, const float* __restrict__ W,
            const float* __restrict__ att_src,
            const float* __restrict__ att_dst, int n) {
    extern __shared__ uint32_t sm[];
    uint32_t* sXh = sm;                              // 64 x SX_STR
    uint32_t* sXl = sXh + 64 * SX_STR;
    uint32_t* sWh = sXl + 64 * SX_STR;               // 64 x SW_STR
    uint32_t* sWl = sWh + 64 * SW_STR;

    int t = threadIdx.x;
    int lane = t & 31;
    int wid = t >> 5;
    int wm = wid >> 2;        // 0..1   (M group: rows wm*32 .. +32)
    int wn = wid & 3;         // 0..3   (N group / head: cols wn*64 .. +64)
    int row0 = blockIdx.x * 64;

    // ---- Stage x tile (64x64) as tf32 hi+lo ----
#pragma unroll
    for (int i = 0; i < 4; i++) {
        int idx4 = t + i * 256;           // float4 index; row = idx4/16
        int r = idx4 >> 4, c = (idx4 & 15) * 4;
        float4 v = make_float4(0.f, 0.f, 0.f, 0.f);
        if (row0 + r < n) v = *(const float4*)(x + (size_t)(row0 + r) * D_IN + c);
        uint32_t* ph = sXh + r * SX_STR + c;
        uint32_t* pl = sXl + r * SX_STR + c;
        float vf[4] = {v.x, v.y, v.z, v.w};
#pragma unroll
        for (int k = 0; k < 4; k++) {
            uint32_t hi = f2tf32(vf[k]);
            ph[k] = hi;
            pl[k] = f2tf32(vf[k] - __uint_as_float(hi));
        }
    }

    // ---- Stage W (64x256) as tf32 hi+lo ----
#pragma unroll
    for (int i = 0; i < 16; i++) {
        int idx4 = t + i * 256;           // float4 index; row = idx4/64
        int r = idx4 >> 6, c = (idx4 & 63) * 4;
        float4 v = *(const float4*)(W + (size_t)r * HC + c);
        uint32_t* ph = sWh + r * SW_STR + c;
        uint32_t* pl = sWl + r * SW_STR + c;
        float vf[4] = {v.x, v.y, v.z, v.w};
#pragma unroll
        for (int k = 0; k < 4; k++) {
            uint32_t hi = f2tf32(vf[k]);
            ph[k] = hi;
            pl[k] = f2tf32(vf[k] - __uint_as_float(hi));
        }
    }
    __syncthreads();

    // ---- MMA mainloop ----
    float acc[2][8][4];
#pragma unroll
    for (int mt = 0; mt < 2; mt++)
#pragma unroll
        for (int nt = 0; nt < 8; nt++)
#pragma unroll
            for (int k = 0; k < 4; k++) acc[mt][nt][k] = 0.f;

    int qr = lane >> 2;   // 0..7  (quad row)
    int ql = lane & 3;    // 0..3  (quad lane)

#pragma unroll
    for (int kc = 0; kc < 8; kc++) {
        int k0 = kc * 8;
        // A fragments (hi, lo): row-major 16x8
        uint32_t ah[2][4], al[2][4];
#pragma unroll
        for (int mt = 0; mt < 2; mt++) {
            int rbase = wm * 32 + mt * 16 + qr;
            const uint32_t* ph = sXh + rbase * SX_STR + k0 + ql;
            const uint32_t* pl = sXl + rbase * SX_STR + k0 + ql;
            ah[mt][0] = ph[0];             al[mt][0] = pl[0];
            ah[mt][1] = ph[8 * SX_STR];    al[mt][1] = pl[8 * SX_STR];
            ah[mt][2] = ph[4];             al[mt][2] = pl[4];
            ah[mt][3] = ph[8 * SX_STR + 4];al[mt][3] = pl[8 * SX_STR + 4];
        }
        // B fragments (hi, lo): k-major 8x8
        uint32_t bh[8][2], bl[8][2];
#pragma unroll
        for (int nt = 0; nt < 8; nt++) {
            int nbase = wn * 64 + nt * 8 + qr;
            const uint32_t* ph = sWh + (k0 + ql) * SW_STR + nbase;
            const uint32_t* pl = sWl + (k0 + ql) * SW_STR + nbase;
            bh[nt][0] = ph[0];             bl[nt][0] = pl[0];
            bh[nt][1] = ph[4 * SW_STR];    bl[nt][1] = pl[4 * SW_STR];
        }
#pragma unroll
        for (int mt = 0; mt < 2; mt++)
#pragma unroll
            for (int nt = 0; nt < 8; nt++) {
                float* c = acc[mt][nt];
                // hi*hi
                asm volatile(
                    "mma.sync.aligned.m16n8k8.row.col.f32.tf32.tf32.f32 "
                    "{%0,%1,%2,%3}, {%4,%5,%6,%7}, {%8,%9}, {%0,%1,%2,%3};"
                    : "+f"(c[0]), "+f"(c[1]), "+f"(c[2]), "+f"(c[3])
                    : "r"(ah[mt][0]), "r"(ah[mt][1]), "r"(ah[mt][2]), "r"(ah[mt][3]),
                      "r"(bh[nt][0]), "r"(bh[nt][1]));
                // hi*lo
                asm volatile(
                    "mma.sync.aligned.m16n8k8.row.col.f32.tf32.tf32.f32 "
                    "{%0,%1,%2,%3}, {%4,%5,%6,%7}, {%8,%9}, {%0,%1,%2,%3};"
                    : "+f"(c[0]), "+f"(c[1]), "+f"(c[2]), "+f"(c[3])
                    : "r"(ah[mt][0]), "r"(ah[mt][1]), "r"(ah[mt][2]), "r"(ah[mt][3]),
                      "r"(bl[nt][0]), "r"(bl[nt][1]));
                // lo*hi
                asm volatile(
                    "mma.sync.aligned.m16n8k8.row.col.f32.tf32.tf32.f32 "
                    "{%0,%1,%2,%3}, {%4,%5,%6,%7}, {%8,%9}, {%0,%1,%2,%3};"
                    : "+f"(c[0]), "+f"(c[1]), "+f"(c[2]), "+f"(c[3])
                    : "r"(al[mt][0]), "r"(al[mt][1]), "r"(al[mt][2]), "r"(al[mt][3]),
                      "r"(bh[nt][0]), "r"(bh[nt][1]));
            }
    }

    // ---- Store xl (fp16) + fused attention dots (fp32 accs) ----
    float ps[4], pd[4];   // per local row instance: [mt*2 + (0: qr, 1: qr+8)]
#pragma unroll
    for (int k = 0; k < 4; k++) { ps[k] = 0.f; pd[k] = 0.f; }

#pragma unroll
    for (int mt = 0; mt < 2; mt++) {
        int r_lo = row0 + wm * 32 + mt * 16 + qr;
#pragma unroll
        for (int nt = 0; nt < 8; nt++) {
            int col = wn * 64 + nt * 8 + 2 * ql;      // global col
            int cl = nt * 8 + 2 * ql;                  // col within head
            const float* c = acc[mt][nt];
            float a0s = att_src[wn * 64 + cl], a1s = att_src[wn * 64 + cl + 1];
            float a0d = att_dst[wn * 64 + cl], a1d = att_dst[wn * 64 + cl + 1];
            ps[mt * 2 + 0] += c[0] * a0s + c[1] * a1s;
            pd[mt * 2 + 0] += c[0] * a0d + c[1] * a1d;
            ps[mt * 2 + 1] += c[2] * a0s + c[3] * a1s;
            pd[mt * 2 + 1] += c[2] * a0d + c[3] * a1d;
            if (r_lo < n)
                *(__half2*)(g_xlh + (size_t)r_lo * HC + col) = __floats2half2_rn(c[0], c[1]);
            if (r_lo + 8 < n)
                *(__half2*)(g_xlh + (size_t)(r_lo + 8) * HC + col) = __floats2half2_rn(c[2], c[3]);
        }
    }

    // Quad reduction (4 lanes share a row)
#pragma unroll
    for (int k = 0; k < 4; k++) {
#pragma unroll
        for (int off = 2; off > 0; off >>= 1) {
            ps[k] += __shfl_down_sync(0xffffffffu, ps[k], off, 4);
            pd[k] += __shfl_down_sync(0xffffffffu, pd[k], off, 4);
        }
    }
    if (ql == 0) {
#pragma unroll
        for (int mt = 0; mt < 2; mt++) {
            int r_lo = row0 + wm * 32 + mt * 16 + qr;
            if (r_lo < n) {
                g_asrc[r_lo * HEADS + wn] = ps[mt * 2 + 0];
                g_adst[r_lo * HEADS + wn] = pd[mt * 2 + 0];
            }
            if (r_lo + 8 < n) {
                g_asrc[(r_lo + 8) * HEADS + wn] = ps[mt * 2 + 1];
                g_adst[(r_lo + 8) * HEADS + wn] = pd[mt * 2 + 1];
            }
        }
    }
}

// ---------------------------------------------------------------------------
// 6. Aggregate, warp per destination node, online softmax, pipelined.
//    lane handles channels [lane*8, lane*8+8) as fp16 (one uint4 gather).
//    Degree-0 nodes get bias.
// ---------------------------------------------------------------------------
__global__ void agg_kernel(const float* __restrict__ bias, float* __restrict__ out, int N) {
    int w = (blockIdx.x * blockDim.x + threadIdx.x) >> 5;
    int lane = threadIdx.x & 31;
    if (w >= N) return;

    const float* bp = bias + lane * 8;
    float4 b0 = *(const float4*)bp;
    float4 b1 = *(const float4*)(bp + 4);
    float* po = out + (size_t)w * HC + lane * 8;

    int beg = g_off[w];
    int end = g_off[w + 1];
    if (beg == end) {
        *(float4*)po = b0;
        *(float4*)(po + 4) = b1;
        return;
    }

    int h = lane >> 3;
    float adh = g_adst[w * HEADS + h];

    float m = -FLT_MAX;
    float den = 0.f;
    float acc[8];
#pragma unroll
    for (int k = 0; k < 8; k++) acc[k] = 0.f;

    // Software pipeline: prefetch next src id + src score.
    int s_nxt = g_srclist[beg];
    float a_nxt = g_asrc[s_nxt * HEADS + h];

    for (int i = beg; i < end; i++) {
        int s = s_nxt;
        float a = a_nxt;
        if (i + 1 < end) {
            s_nxt = g_srclist[i + 1];
            a_nxt = g_asrc[s_nxt * HEADS + h];
        }

        float l = a + adh;
        l = (l >= 0.f) ? l : 0.2f * l;

        float m_new = fmaxf(m, l);
        float scale = __expf(m - m_new);     // 1 if no new max; 0 on first iter
        float we = __expf(l - m_new);
        den = den * scale + we;

        uint4 pk = *(const uint4*)(g_xlh + (size_t)s * HC + lane * 8);
        float2 f0 = __half22float2(*(__half2*)&pk.x);
        float2 f1 = __half22float2(*(__half2*)&pk.y);
        float2 f2 = __half22float2(*(__half2*)&pk.z);
        float2 f3 = __half22float2(*(__half2*)&pk.w);
        acc[0] = acc[0] * scale + we * f0.x;
        acc[1] = acc[1] * scale + we * f0.y;
        acc[2] = acc[2] * scale + we * f1.x;
        acc[3] = acc[3] * scale + we * f1.y;
        acc[4] = acc[4] * scale + we * f2.x;
        acc[5] = acc[5] * scale + we * f2.y;
        acc[6] = acc[6] * scale + we * f3.x;
        acc[7] = acc[7] * scale + we * f3.y;
        m = m_new;
    }

    float inv = 1.f / (den + 1e-16f);
    float4 o0 = make_float4(acc[0] * inv + b0.x, acc[1] * inv + b0.y,
                            acc[2] * inv + b0.z, acc[3] * inv + b0.w);
    float4 o1 = make_float4(acc[4] * inv + b1.x, acc[5] * inv + b1.y,
                            acc[6] * inv + b1.z, acc[7] * inv + b1.w);
    *(float4*)po = o0;
    *(float4*)(po + 4) = o1;
}

// ---------------------------------------------------------------------------
// Launch
// ---------------------------------------------------------------------------
extern "C" void kernel_launch(void* const* d_in, const int* in_sizes, int n_in,
                              void* d_out, int out_size) {
    const float* x        = (const float*)d_in[0];
    const void*  ei       = (const void*)d_in[1];
    const float* W        = (const float*)d_in[2];
    const float* att_src  = (const float*)d_in[3];
    const float* att_dst  = (const float*)d_in[4];
    const float* bias     = (const float*)d_in[5];
    float* out = (float*)d_out;

    int N = in_sizes[0] / D_IN;
    int E = in_sizes[1] / 2;

    detect_kernel<<<1, 1>>>(ei);
    init_kernel<<<(N + 255) / 256, 256>>>(N);
    count_kernel<<<(E + 255) / 256, 256>>>(ei, E);

    int nb = (N + SCAN_B - 1) / SCAN_B;   // 98 for N=100000
    scan1_kernel<<<nb, SCAN_B>>>(N);
    scan2_kernel<<<1, 128>>>(nb, N, E);
    scan3_kernel<<<nb, SCAN_B>>>(N);

    scatter_kernel<<<(E + 255) / 256, 256>>>(ei, E);

    size_t smem = ((size_t)64 * SX_STR + (size_t)64 * SW_STR) * 4 * 2;  // ~166 KB
    cudaFuncSetAttribute(gemm_kernel, cudaFuncAttributeMaxDynamicSharedMemorySize, (int)smem);
    gemm_kernel<<<(N + 63) / 64, 256, smem>>>(x, W, att_src, att_dst, N);

    long long agg_threads = (long long)N * 32;
    agg_kernel<<<(int)((agg_threads + 255) / 256), 256>>>(bias, out, N);
}

// round 6
// speedup vs baseline: 3.3815x; 1.0875x over previous
#include <cuda_runtime.h>
#include <cuda_fp16.h>
#include <math.h>
#include <float.h>
#include <stdint.h>

// Problem constants (GAT_38585986187787)
#define MAX_NODES 100000
#define MAX_EDGES 1600000
#define D_IN 64
#define HEADS 4
#define HC 256   // HEADS * C_OUT
#define SCAN_B 1024
#define MAX_SCAN_BLOCKS 128

// smem strides in uint32 units (bank-conflict-free fragment loads)
#define SX_STR 68    // 68 % 32 == 4  -> bank = 4*row + k, distinct for 8x4 lanes
#define SW_STR 264   // 264 % 32 == 8 -> bank = 8*k + n,  distinct for 4x8 lanes

// ---------------------------------------------------------------------------
// Device scratch
// ---------------------------------------------------------------------------
__device__ __half g_xlh[(size_t)MAX_NODES * HC];    // 51.2 MB   x @ W (fp16)
__device__ float g_asrc[MAX_NODES * HEADS];         // 1.6 MB
__device__ float g_adst[MAX_NODES * HEADS];         // 1.6 MB
__device__ int   g_cnt[MAX_NODES];                  // in-degree counts
__device__ int   g_off[MAX_NODES + 1];              // CSR offsets (by dst)
__device__ int   g_cur[MAX_NODES];                  // scatter cursors
__device__ int   g_srclist[MAX_EDGES];              // src id per CSR slot
__device__ int   g_bsum[MAX_SCAN_BLOCKS];           // scan block sums
__device__ int   g_bpre[MAX_SCAN_BLOCKS];           // scan block prefixes
__device__ int   g_is64;                            // edge_index dtype flag

__device__ __forceinline__ long long load_edge(const void* ei, int is64, size_t idx) {
    if (is64) return ((const long long*)ei)[idx];
    return (long long)(((const int*)ei)[idx]);
}

__device__ __forceinline__ uint32_t f2tf32(float f) {
    uint32_t r;
    asm("cvt.rna.tf32.f32 %0, %1;" : "=r"(r) : "f"(f));
    return r;
}

__device__ __forceinline__ float leaky(float v) {
    return (v >= 0.f) ? v : 0.2f * v;
}

// ---------------------------------------------------------------------------
// 1. Init (+ fused dtype detect): zero degree counters
// ---------------------------------------------------------------------------
__global__ void init_kernel(const void* ei, int n) {
    int idx = blockIdx.x * blockDim.x + threadIdx.x;
    if (idx == 0) {
        const unsigned long long* p = (const unsigned long long*)ei;
        bool ok = true;
#pragma unroll
        for (int i = 0; i < 16; i++) ok = ok && (p[i] < (unsigned long long)MAX_NODES);
        g_is64 = ok ? 1 : 0;
    }
    if (idx < n) g_cnt[idx] = 0;
}

// ---------------------------------------------------------------------------
// 2. Count in-degrees (2 edges per thread)
// ---------------------------------------------------------------------------
__global__ void count_kernel(const void* __restrict__ ei, int E) {
    int e = (blockIdx.x * blockDim.x + threadIdx.x) * 2;
    if (e >= E) return;
    int is64 = g_is64;
    if (e + 1 < E) {
        int d0, d1;
        if (is64) {
            longlong2 p = *(const longlong2*)((const long long*)ei + (size_t)E + e);
            d0 = (int)p.x; d1 = (int)p.y;
        } else {
            int2 p = *(const int2*)((const int*)ei + (size_t)E + e);
            d0 = p.x; d1 = p.y;
        }
        atomicAdd(&g_cnt[d0], 1);
        atomicAdd(&g_cnt[d1], 1);
    } else {
        int d = (int)load_edge(ei, is64, (size_t)E + e);
        atomicAdd(&g_cnt[d], 1);
    }
}

// ---------------------------------------------------------------------------
// 3a. Block-local exclusive scan (shfl-based), block sums to g_bsum
// ---------------------------------------------------------------------------
__global__ void scan1_kernel(int N) {
    int t = threadIdx.x;
    int i = blockIdx.x * SCAN_B + t;
    int lane = t & 31, wid = t >> 5;

    int v = (i < N) ? g_cnt[i] : 0;
    int x = v;
#pragma unroll
    for (int off = 1; off < 32; off <<= 1) {
        int u = __shfl_up_sync(0xffffffffu, x, off);
        if (lane >= off) x += u;
    }
    __shared__ int wsum[32];
    if (lane == 31) wsum[wid] = x;
    __syncthreads();
    if (wid == 0) {
        int y = wsum[lane];
#pragma unroll
        for (int off = 1; off < 32; off <<= 1) {
            int u = __shfl_up_sync(0xffffffffu, y, off);
            if (lane >= off) y += u;
        }
        wsum[lane] = y;
    }
    __syncthreads();
    int base = (wid > 0) ? wsum[wid - 1] : 0;
    int incl = base + x;
    if (i < N) g_off[i] = incl - v;           // local exclusive, no block base yet
    if (t == SCAN_B - 1) g_bsum[blockIdx.x] = incl;
}

// ---------------------------------------------------------------------------
// 3b. Scan the block sums (nb <= 128), one block of 128 threads
// ---------------------------------------------------------------------------
__global__ void scan2_kernel(int nb, int N, int E) {
    int t = threadIdx.x, lane = t & 31, wid = t >> 5;
    int v = (t < nb) ? g_bsum[t] : 0;
    int x = v;
#pragma unroll
    for (int off = 1; off < 32; off <<= 1) {
        int u = __shfl_up_sync(0xffffffffu, x, off);
        if (lane >= off) x += u;
    }
    __shared__ int ws[4];
    __shared__ int wpre[4];
    if (lane == 31) ws[wid] = x;
    __syncthreads();
    if (t == 0) {
        int s = 0;
#pragma unroll
        for (int k = 0; k < 4; k++) { wpre[k] = s; s += ws[k]; }
    }
    __syncthreads();
    int incl = wpre[wid] + x;
    if (t < nb) g_bpre[t] = incl - v;
    if (t == 0) g_off[N] = E;
}

// ---------------------------------------------------------------------------
// 3c. Add block bases, emit cursors
// ---------------------------------------------------------------------------
__global__ void scan3_kernel(int N) {
    int i = blockIdx.x * SCAN_B + threadIdx.x;
    if (i < N) {
        int o = g_off[i] + g_bpre[blockIdx.x];
        g_off[i] = o;
        g_cur[i] = o;
    }
}

// ---------------------------------------------------------------------------
// 4. Scatter src ids into CSR slots (2 edges per thread)
// ---------------------------------------------------------------------------
__global__ void scatter_kernel(const void* __restrict__ ei, int E) {
    int e = (blockIdx.x * blockDim.x + threadIdx.x) * 2;
    if (e >= E) return;
    int is64 = g_is64;
    if (e + 1 < E) {
        int s0, s1, d0, d1;
        if (is64) {
            longlong2 ps = *(const longlong2*)((const long long*)ei + e);
            longlong2 pd = *(const longlong2*)((const long long*)ei + (size_t)E + e);
            s0 = (int)ps.x; s1 = (int)ps.y; d0 = (int)pd.x; d1 = (int)pd.y;
        } else {
            int2 ps = *(const int2*)((const int*)ei + e);
            int2 pd = *(const int2*)((const int*)ei + (size_t)E + e);
            s0 = ps.x; s1 = ps.y; d0 = pd.x; d1 = pd.y;
        }
        int p0 = atomicAdd(&g_cur[d0], 1);
        int p1 = atomicAdd(&g_cur[d1], 1);
        g_srclist[p0] = s0;
        g_srclist[p1] = s1;
    } else {
        int s = (int)load_edge(ei, is64, e);
        int d = (int)load_edge(ei, is64, (size_t)E + e);
        int pos = atomicAdd(&g_cur[d], 1);
        g_srclist[pos] = s;
    }
}

// ---------------------------------------------------------------------------
// 5. TF32 tensor-core GEMM + fused attention scores (single-precision-level
//    not needed; plain tf32). xl stored as fp16.
//    Block: 256 thr (8 warps), tile M=64, N=256, K=64. Warp grid 2(M) x 4(N).
// ---------------------------------------------------------------------------
__global__ void __launch_bounds__(256, 2)
gemm_kernel(const float* __restrict__ x, const float* __restrict__ W,
            const float* __restrict__ att_src,
            const float* __restrict__ att_dst, int n) {
    extern __shared__ uint32_t sm[];
    uint32_t* sX = sm;                    // 64 x SX_STR
    uint32_t* sW = sm + 64 * SX_STR;      // 64 x SW_STR

    int t = threadIdx.x;
    int lane = t & 31;
    int wid = t >> 5;
    int wm = wid >> 2;        // 0..1   (M group: rows wm*32 .. +32)
    int wn = wid & 3;         // 0..3   (N group / head: cols wn*64 .. +64)
    int row0 = blockIdx.x * 64;

    // ---- Stage x tile (64x64) as tf32 ----
#pragma unroll
    for (int i = 0; i < 4; i++) {
        int idx4 = t + i * 256;
        int r = idx4 >> 4, c = (idx4 & 15) * 4;
        float4 v = make_float4(0.f, 0.f, 0.f, 0.f);
        if (row0 + r < n) v = *(const float4*)(x + (size_t)(row0 + r) * D_IN + c);
        uint32_t* p = sX + r * SX_STR + c;
        p[0] = f2tf32(v.x); p[1] = f2tf32(v.y); p[2] = f2tf32(v.z); p[3] = f2tf32(v.w);
    }

    // ---- Stage W (64x256) as tf32 ----
#pragma unroll
    for (int i = 0; i < 16; i++) {
        int idx4 = t + i * 256;
        int r = idx4 >> 6, c = (idx4 & 63) * 4;
        float4 v = *(const float4*)(W + (size_t)r * HC + c);
        uint32_t* p = sW + r * SW_STR + c;
        p[0] = f2tf32(v.x); p[1] = f2tf32(v.y); p[2] = f2tf32(v.z); p[3] = f2tf32(v.w);
    }
    __syncthreads();

    float acc[2][8][4];
#pragma unroll
    for (int mt = 0; mt < 2; mt++)
#pragma unroll
        for (int nt = 0; nt < 8; nt++)
#pragma unroll
            for (int k = 0; k < 4; k++) acc[mt][nt][k] = 0.f;

    int qr = lane >> 2;   // 0..7  (quad row)
    int ql = lane & 3;    // 0..3  (quad lane)

#pragma unroll
    for (int kc = 0; kc < 8; kc++) {
        int k0 = kc * 8;
        uint32_t a[2][4];
#pragma unroll
        for (int mt = 0; mt < 2; mt++) {
            int rbase = wm * 32 + mt * 16 + qr;
            const uint32_t* pa = sX + rbase * SX_STR + k0 + ql;
            a[mt][0] = pa[0];
            a[mt][1] = pa[8 * SX_STR];
            a[mt][2] = pa[4];
            a[mt][3] = pa[8 * SX_STR + 4];
        }
        uint32_t b[8][2];
#pragma unroll
        for (int nt = 0; nt < 8; nt++) {
            int nbase = wn * 64 + nt * 8 + qr;
            const uint32_t* pb = sW + (k0 + ql) * SW_STR + nbase;
            b[nt][0] = pb[0];
            b[nt][1] = pb[4 * SW_STR];
        }
#pragma unroll
        for (int mt = 0; mt < 2; mt++)
#pragma unroll
            for (int nt = 0; nt < 8; nt++) {
                float* c = acc[mt][nt];
                asm volatile(
                    "mma.sync.aligned.m16n8k8.row.col.f32.tf32.tf32.f32 "
                    "{%0,%1,%2,%3}, {%4,%5,%6,%7}, {%8,%9}, {%0,%1,%2,%3};"
                    : "+f"(c[0]), "+f"(c[1]), "+f"(c[2]), "+f"(c[3])
                    : "r"(a[mt][0]), "r"(a[mt][1]), "r"(a[mt][2]), "r"(a[mt][3]),
                      "r"(b[nt][0]), "r"(b[nt][1]));
            }
    }

    // ---- Store xl (fp16) + fused attention dots ----
    float ps[4], pd[4];
#pragma unroll
    for (int k = 0; k < 4; k++) { ps[k] = 0.f; pd[k] = 0.f; }

#pragma unroll
    for (int mt = 0; mt < 2; mt++) {
        int r_lo = row0 + wm * 32 + mt * 16 + qr;
#pragma unroll
        for (int nt = 0; nt < 8; nt++) {
            int col = wn * 64 + nt * 8 + 2 * ql;
            int cl = nt * 8 + 2 * ql;
            const float* c = acc[mt][nt];
            float a0s = att_src[wn * 64 + cl], a1s = att_src[wn * 64 + cl + 1];
            float a0d = att_dst[wn * 64 + cl], a1d = att_dst[wn * 64 + cl + 1];
            ps[mt * 2 + 0] += c[0] * a0s + c[1] * a1s;
            pd[mt * 2 + 0] += c[0] * a0d + c[1] * a1d;
            ps[mt * 2 + 1] += c[2] * a0s + c[3] * a1s;
            pd[mt * 2 + 1] += c[2] * a0d + c[3] * a1d;
            if (r_lo < n)
                *(__half2*)(g_xlh + (size_t)r_lo * HC + col) = __floats2half2_rn(c[0], c[1]);
            if (r_lo + 8 < n)
                *(__half2*)(g_xlh + (size_t)(r_lo + 8) * HC + col) = __floats2half2_rn(c[2], c[3]);
        }
    }

#pragma unroll
    for (int k = 0; k < 4; k++) {
#pragma unroll
        for (int off = 2; off > 0; off >>= 1) {
            ps[k] += __shfl_down_sync(0xffffffffu, ps[k], off, 4);
            pd[k] += __shfl_down_sync(0xffffffffu, pd[k], off, 4);
        }
    }
    if (ql == 0) {
#pragma unroll
        for (int mt = 0; mt < 2; mt++) {
            int r_lo = row0 + wm * 32 + mt * 16 + qr;
            if (r_lo < n) {
                g_asrc[r_lo * HEADS + wn] = ps[mt * 2 + 0];
                g_adst[r_lo * HEADS + wn] = pd[mt * 2 + 0];
            }
            if (r_lo + 8 < n) {
                g_asrc[(r_lo + 8) * HEADS + wn] = ps[mt * 2 + 1];
                g_adst[(r_lo + 8) * HEADS + wn] = pd[mt * 2 + 1];
            }
        }
    }
}

// ---------------------------------------------------------------------------
// 6. Aggregate v2, warp per destination node.
//    Phase 1: lane-parallel segment max (all 4 heads at once, warp-reduced).
//    Phase 2: plain exp-weighted accumulate (no serial rescale chain),
//             xl gather prefetched one edge ahead.
// ---------------------------------------------------------------------------
__global__ void agg_kernel(const float* __restrict__ bias, float* __restrict__ out, int N) {
    int w = (blockIdx.x * blockDim.x + threadIdx.x) >> 5;
    int lane = threadIdx.x & 31;
    if (w >= N) return;

    const float* bp = bias + lane * 8;
    float4 b0 = *(const float4*)bp;
    float4 b1 = *(const float4*)(bp + 4);
    float* po = out + (size_t)w * HC + lane * 8;

    int beg = g_off[w];
    int end = g_off[w + 1];
    if (beg == end) {
        *(float4*)po = b0;
        *(float4*)(po + 4) = b1;
        return;
    }

    float4 ad4 = *(const float4*)(g_adst + w * HEADS);

    // ---- Phase 1: segment max over all 4 heads, lanes parallel over edges ----
    float4 mx = make_float4(-FLT_MAX, -FLT_MAX, -FLT_MAX, -FLT_MAX);
    for (int i = beg + lane; i < end; i += 32) {
        int s = g_srclist[i];
        float4 as = *(const float4*)(g_asrc + s * HEADS);
        mx.x = fmaxf(mx.x, leaky(as.x + ad4.x));
        mx.y = fmaxf(mx.y, leaky(as.y + ad4.y));
        mx.z = fmaxf(mx.z, leaky(as.z + ad4.z));
        mx.w = fmaxf(mx.w, leaky(as.w + ad4.w));
    }
#pragma unroll
    for (int off = 16; off > 0; off >>= 1) {
        mx.x = fmaxf(mx.x, __shfl_xor_sync(0xffffffffu, mx.x, off));
        mx.y = fmaxf(mx.y, __shfl_xor_sync(0xffffffffu, mx.y, off));
        mx.z = fmaxf(mx.z, __shfl_xor_sync(0xffffffffu, mx.z, off));
        mx.w = fmaxf(mx.w, __shfl_xor_sync(0xffffffffu, mx.w, off));
    }

    int h = lane >> 3;
    float m   = (h == 0) ? mx.x  : (h == 1) ? mx.y  : (h == 2) ? mx.z  : mx.w;
    float adh = (h == 0) ? ad4.x : (h == 1) ? ad4.y : (h == 2) ? ad4.z : ad4.w;

    // ---- Phase 2: exp-weighted accumulate, prefetch 1 edge ahead ----
    float den = 0.f;
    float acc[8];
#pragma unroll
    for (int k = 0; k < 8; k++) acc[k] = 0.f;

    int s_cur = g_srclist[beg];
    float a_cur = g_asrc[s_cur * HEADS + h];
    uint4 pk_cur = *(const uint4*)(g_xlh + (size_t)s_cur * HC + lane * 8);

    for (int i = beg; i < end; i++) {
        int s_n = 0; float a_n = 0.f; uint4 pk_n = make_uint4(0, 0, 0, 0);
        if (i + 1 < end) {
            s_n = g_srclist[i + 1];
            a_n = g_asrc[s_n * HEADS + h];
            pk_n = *(const uint4*)(g_xlh + (size_t)s_n * HC + lane * 8);
        }

        float l = leaky(a_cur + adh);
        float we = __expf(l - m);
        den += we;

        float2 f0 = __half22float2(*(__half2*)&pk_cur.x);
        float2 f1 = __half22float2(*(__half2*)&pk_cur.y);
        float2 f2 = __half22float2(*(__half2*)&pk_cur.z);
        float2 f3 = __half22float2(*(__half2*)&pk_cur.w);
        acc[0] += we * f0.x;
        acc[1] += we * f0.y;
        acc[2] += we * f1.x;
        acc[3] += we * f1.y;
        acc[4] += we * f2.x;
        acc[5] += we * f2.y;
        acc[6] += we * f3.x;
        acc[7] += we * f3.y;

        s_cur = s_n; a_cur = a_n; pk_cur = pk_n;
    }

    float inv = 1.f / (den + 1e-16f);
    float4 o0 = make_float4(acc[0] * inv + b0.x, acc[1] * inv + b0.y,
                            acc[2] * inv + b0.z, acc[3] * inv + b0.w);
    float4 o1 = make_float4(acc[4] * inv + b1.x, acc[5] * inv + b1.y,
                            acc[6] * inv + b1.z, acc[7] * inv + b1.w);
    *(float4*)po = o0;
    *(float4*)(po + 4) = o1;
}

// ---------------------------------------------------------------------------
// Launch.  NOTE: gemm is deliberately the 4th launch (ncu profiles launch #4).
// ---------------------------------------------------------------------------
extern "C" void kernel_launch(void* const* d_in, const int* in_sizes, int n_in,
                              void* d_out, int out_size) {
    const float* x        = (const float*)d_in[0];
    const void*  ei       = (const void*)d_in[1];
    const float* W        = (const float*)d_in[2];
    const float* att_src  = (const float*)d_in[3];
    const float* att_dst  = (const float*)d_in[4];
    const float* bias     = (const float*)d_in[5];
    float* out = (float*)d_out;

    int N = in_sizes[0] / D_IN;
    int E = in_sizes[1] / 2;

    init_kernel<<<(N + 255) / 256, 256>>>(ei, N);                 // 1
    count_kernel<<<(E / 2 + 256) / 256, 256>>>(ei, E);            // 2

    int nb = (N + SCAN_B - 1) / SCAN_B;   // 98 for N=100000
    scan1_kernel<<<nb, SCAN_B>>>(N);                              // 3

    size_t smem = ((size_t)64 * SX_STR + (size_t)64 * SW_STR) * 4;  // ~85 KB
    cudaFuncSetAttribute(gemm_kernel, cudaFuncAttributeMaxDynamicSharedMemorySize, (int)smem);
    gemm_kernel<<<(N + 63) / 64, 256, smem>>>(x, W, att_src, att_dst, N);  // 4 (profiled)

    scan2_kernel<<<1, 128>>>(nb, N, E);                           // 5
    scan3_kernel<<<nb, SCAN_B>>>(N);                              // 6
    scatter_kernel<<<(E / 2 + 256) / 256, 256>>>(ei, E);          // 7

    long long agg_threads = (long long)N * 32;
    agg_kernel<<<(int)((agg_threads + 255) / 256), 256>>>(bias, out, N);   // 8
}